// round 15
// baseline (speedup 1.0000x reference)
#include <cuda_runtime.h>
#include <math.h>

typedef unsigned long long ull;
typedef unsigned int u32;

#define MAXN_PAD 75008   // 293 blocks * 256 rows

// Global scratch (static __device__ arrays: never allocated at runtime)
__device__ float g_agg[(size_t)MAXN_PAD * 512];   // 153.6 MB
__device__ float g_h  [(size_t)MAXN_PAD * 64];    // 19.2 MB
__device__ ull   g_W1p[256 * 64];                 // W1 k-pair packed [kp][64]
__device__ ull   g_W2p[16 * 16 * 48];             // W2 packed [ch][kp][48] (pad 6/grp)

__device__ __forceinline__ ull pk2(float x, float y) {
    ull r; asm("mov.b64 %0, {%1, %2};" : "=l"(r) : "f"(x), "f"(y)); return r;
}
__device__ __forceinline__ void upk2(ull v, float& x, float& y) {
    asm("mov.b64 {%0, %1}, %2;" : "=f"(x), "=f"(y) : "l"(v));
}
__device__ __forceinline__ void ffma2(ull& d, ull a, ull b) {
    asm("fma.rn.f32x2 %0, %1, %2, %0;" : "+l"(d) : "l"(a), "l"(b));
}
__device__ __forceinline__ void fadd2(ull& d, ull a) {
    asm("add.rn.f32x2 %0, %0, %1;" : "+l"(d) : "l"(a));
}
__device__ __forceinline__ u32 smem_u32(const void* p) {
    u32 a;
    asm("{ .reg .u64 t; cvta.to.shared.u64 t, %1; cvt.u32.u64 %0, t; }" : "=r"(a) : "l"(p));
    return a;
}
__device__ __forceinline__ void cp16(u32 dst, const void* src) {
    asm volatile("cp.async.cg.shared.global [%0], [%1], 16;" :: "r"(dst), "l"(src));
}
__device__ __forceinline__ void cp_commit() { asm volatile("cp.async.commit_group;"); }
__device__ __forceinline__ void cp_wait0()  { asm volatile("cp.async.wait_group 0;"); }

// L2 eviction policy (evict_last) for gather loads — createpolicy + cache_hint
__device__ __forceinline__ ull mkpolicy_el() {
    ull p;
    asm("createpolicy.fractional.L2::evict_last.b64 %0, 1.0;" : "=l"(p));
    return p;
}
__device__ __forceinline__ ull ldg_el(const float* p, ull pol) {
    ull v;
    asm volatile("ld.global.nc.L2::cache_hint.b64 %0, [%1], %2;"
                 : "=l"(v) : "l"(p), "l"(pol));
    return v;
}
// streaming store: evict-first, don't pollute L2
__device__ __forceinline__ void stcs(float* p, ull v) {
    asm volatile("st.global.cs.b64 [%0], %1;" :: "l"(p), "l"(v) : "memory");
}

// ---------------------------------------------------------------------------
// W prep (single launch): k-pair pack both weights into GEMM SMEM layout
// ---------------------------------------------------------------------------
__global__ void prep_kernel(const float* __restrict__ W1, const float* __restrict__ W2,
                            ull* __restrict__ Wp1, ull* __restrict__ Wp2)
{
    int b = blockIdx.x;
    if (b < 64) {
        int i = b * 256 + threadIdx.x;           // 16384
        int kp = i >> 6, c = i & 63;
        Wp1[i] = pk2(W1[(size_t)(2 * kp) * 64 + c], W1[(size_t)(2 * kp + 1) * 64 + c]);
    } else {
        int i = (b - 64) * 256 + threadIdx.x;    // 10240
        if (i < 256 * 40) {
            int kp = i / 40, c = i % 40;
            int ch = kp >> 4, kl = kp & 15;
            Wp2[ch * 768 + kl * 48 + (c / 5) * 6 + (c % 5)] =
                pk2(W2[(size_t)(2 * kp) * 40 + c], W2[(size_t)(2 * kp + 1) * 40 + c]);
        }
    }
}

// ---------------------------------------------------------------------------
// Aggregation: one warp per node.
// Phase 1: all 8 ballots.  Phase 2: 8 independent first-loads in flight.
// Phase 3: drain per-relation chains (depth-2 pipelined).
// Writes use .cs (evict-first); reads use cache_hint evict_last -> x/h stays in L2.
// ---------------------------------------------------------------------------
__global__ void __launch_bounds__(256)
agg_kernel(const float* __restrict__ xin,
           const int*   __restrict__ ptr,
           const int*   __restrict__ idx,
           const int*   __restrict__ rel,
           float*       __restrict__ agg,
           int n)
{
    const int node = (blockIdx.x * blockDim.x + threadIdx.x) >> 5;
    const int lane = threadIdx.x & 31;
    if (node >= n) return;

    const ull pol = mkpolicy_el();

    ull acc[8];
    #pragma unroll
    for (int r = 0; r < 8; ++r) acc[r] = 0ull;

    const int e0 = ptr[node], e1 = ptr[node + 1];
    for (int eb = e0; eb < e1; eb += 32) {
        const int cnt = min(32, e1 - eb);
        int mi = 0, mr = -1;
        if (lane < cnt) { mi = idx[eb + lane]; mr = rel[eb + lane]; }

        // phase 1: ballot masks (warp-uniform)
        unsigned m[8];
        #pragma unroll
        for (int r = 0; r < 8; ++r)
            m[r] = __ballot_sync(0xffffffffu, mr == r);

        // phase 2: first load of every nonempty relation (independent LDGs)
        ull v[8];
        #pragma unroll
        for (int r = 0; r < 8; ++r) {
            if (m[r]) {
                int t = __ffs(m[r]) - 1;
                int s = __shfl_sync(0xffffffffu, mi, t);
                v[r] = ldg_el(xin + (size_t)s * 64 + 2 * lane, pol);
            }
        }

        // phase 3: drain chains (next load issued before current add)
        #pragma unroll
        for (int r = 0; r < 8; ++r) {
            unsigned mm = m[r];
            if (!mm) continue;
            unsigned rem = mm & (mm - 1);
            ull cur = v[r];
            while (rem) {
                int t2 = __ffs(rem) - 1; rem &= rem - 1;
                int s2 = __shfl_sync(0xffffffffu, mi, t2);
                ull v2 = ldg_el(xin + (size_t)s2 * 64 + 2 * lane, pol);
                fadd2(acc[r], cur);
                cur = v2;
            }
            fadd2(acc[r], cur);
        }
    }

    float* arow = agg + (size_t)node * 512;
    #pragma unroll
    for (int r = 0; r < 8; ++r)
        stcs(arow + r * 64 + 2 * lane, acc[r]);
}

// ---------------------------------------------------------------------------
// GEMM layer 1: H[256 x 64]/block = relu(A[256 x 512] @ W1), 8 chunks of K=64.
// 256 thr, 8 warps, tile 8x8. cp.async issue interleaved into the kp2 loop.
// ---------------------------------------------------------------------------
__global__ void __launch_bounds__(256, 1)
gemm1_kernel(const float* __restrict__ A,
             const ull*   __restrict__ Wp,   // [256 kp][64] packed
             float*       __restrict__ out,  // g_h
             int n)
{
    extern __shared__ float sm[];
    float* As = sm;                          // [2][16384] floats
    ull*   Bs = (ull*)(sm + 32768);          // [2][2048] ull
    const u32 asb = smem_u32(As);
    const u32 bsb = smem_u32(Bs);

    const int tid  = threadIdx.x;
    const int lane = tid & 31;
    const int w    = tid >> 5;
    const size_t row0 = (size_t)blockIdx.x * 256;

    const int rbase = tid >> 4;              // 0..15 (A stage row base)
    const int c4    = tid & 15;
    const u32 aswz  = (u32)((rbase * 64 + ((c4 ^ (rbase & 7)) << 2)) * 4);

    // bunched prologue stage of chunk 0
    {
        #pragma unroll
        for (int i = 0; i < 16; ++i)
            cp16(asb + aswz + (u32)(i * 4096),
                 A + (row0 + rbase + i * 16) * 512 + c4 * 4);
        #pragma unroll
        for (int i = 0; i < 4; ++i)
            cp16(bsb + (u32)((tid + i * 256) * 16), Wp + (tid + i * 256) * 2);
        cp_commit();
    }

    ull acc[8][8];
    #pragma unroll
    for (int j = 0; j < 8; ++j)
        #pragma unroll
        for (int c = 0; c < 8; ++c) acc[j][c] = 0ull;

    #pragma unroll 1
    for (int ch = 0; ch < 8; ++ch) {
        const int buf = ch & 1;
        cp_wait0();
        __syncthreads();

        const bool st = (ch < 7);
        const u32 ad  = asb + (u32)((buf ^ 1) * 65536) + aswz;
        const float* asrc = A + (row0 + rbase) * 512 + (ch + 1) * 64 + c4 * 4;
        const u32 bd  = bsb + (u32)((buf ^ 1) * 16384 + tid * 16);
        const ull* bsrc = Wp + (size_t)(ch + 1) * 2048 + tid * 2;

        const float* as = As + buf * 16384 + lane * 64;
        const ull*   bs = Bs + buf * 2048 + w * 8;
        #pragma unroll
        for (int kp2 = 0; kp2 < 16; ++kp2) {
            if (st) {
                cp16(ad + (u32)(kp2 * 4096), asrc + kp2 * 16 * 512);
                if (kp2 < 4)
                    cp16(bd + (u32)(kp2 * 4096), bsrc + kp2 * 512);
            }
            ulonglong2 q;
            ull b0[8], b1[8];
            q = *(const ulonglong2*)(bs + (2 * kp2) * 64 + 0); b0[0]=q.x; b0[1]=q.y;
            q = *(const ulonglong2*)(bs + (2 * kp2) * 64 + 2); b0[2]=q.x; b0[3]=q.y;
            q = *(const ulonglong2*)(bs + (2 * kp2) * 64 + 4); b0[4]=q.x; b0[5]=q.y;
            q = *(const ulonglong2*)(bs + (2 * kp2) * 64 + 6); b0[6]=q.x; b0[7]=q.y;
            q = *(const ulonglong2*)(bs + (2 * kp2 + 1) * 64 + 0); b1[0]=q.x; b1[1]=q.y;
            q = *(const ulonglong2*)(bs + (2 * kp2 + 1) * 64 + 2); b1[2]=q.x; b1[3]=q.y;
            q = *(const ulonglong2*)(bs + (2 * kp2 + 1) * 64 + 4); b1[4]=q.x; b1[5]=q.y;
            q = *(const ulonglong2*)(bs + (2 * kp2 + 1) * 64 + 6); b1[6]=q.x; b1[7]=q.y;
            const int swoff = (kp2 ^ (lane & 7)) << 2;
            #pragma unroll
            for (int j = 0; j < 8; ++j) {
                ulonglong2 a = *(const ulonglong2*)(as + j * 2048 + swoff);
                #pragma unroll
                for (int c = 0; c < 8; ++c) {
                    ffma2(acc[j][c], a.x, b0[c]);
                    ffma2(acc[j][c], a.y, b1[c]);
                }
            }
        }
        if (st) cp_commit();
    }

    #pragma unroll
    for (int j = 0; j < 8; ++j) {
        size_t g = row0 + lane + 32 * j;
        float lo, hi; float4 o;
        upk2(acc[j][0], lo, hi); o.x = fmaxf(lo + hi, 0.f);
        upk2(acc[j][1], lo, hi); o.y = fmaxf(lo + hi, 0.f);
        upk2(acc[j][2], lo, hi); o.z = fmaxf(lo + hi, 0.f);
        upk2(acc[j][3], lo, hi); o.w = fmaxf(lo + hi, 0.f);
        *(float4*)(out + g * 64 + w * 8) = o;
        upk2(acc[j][4], lo, hi); o.x = fmaxf(lo + hi, 0.f);
        upk2(acc[j][5], lo, hi); o.y = fmaxf(lo + hi, 0.f);
        upk2(acc[j][6], lo, hi); o.z = fmaxf(lo + hi, 0.f);
        upk2(acc[j][7], lo, hi); o.w = fmaxf(lo + hi, 0.f);
        *(float4*)(out + g * 64 + w * 8 + 4) = o;
    }
}

// ---------------------------------------------------------------------------
// GEMM layer 2 + log_softmax: out[256 x 40]/block, 16 chunks of K=32.
// 256 thr, tile 8x5, 2 CTAs/SM. cp.async issue interleaved into kp2 loop.
// ---------------------------------------------------------------------------
__global__ void __launch_bounds__(256, 2)
gemm2_kernel(const float* __restrict__ A,
             const ull*   __restrict__ Wp,   // [16 ch][16 kp][48] packed
             float*       __restrict__ out,  // [n][40]
             int n)
{
    extern __shared__ float sm[];
    float* As = sm;                          // [2][8192] floats (K=32 chunks)
    ull*   Bs = (ull*)(sm + 16384);          // [2][768] ull
    const u32 asb = smem_u32(As);
    const u32 bsb = smem_u32(Bs);

    const int tid  = threadIdx.x;
    const int lane = tid & 31;
    const int w    = tid >> 5;
    const size_t row0 = (size_t)blockIdx.x * 256;

    const int rbase = tid >> 3;              // 0..31
    const int c4    = tid & 7;
    const u32 aswz  = (u32)((rbase * 32 + ((c4 ^ (rbase & 7)) << 2)) * 4);

    {   // prologue stage chunk 0
        #pragma unroll
        for (int i = 0; i < 8; ++i)
            cp16(asb + aswz + (u32)(i * 4096),
                 A + (row0 + rbase + i * 32) * 512 + c4 * 4);
        #pragma unroll
        for (int i = 0; i < 2; ++i) {
            int v = tid + i * 256;
            if (v < 384) cp16(bsb + (u32)(v * 16), Wp + v * 2);
        }
        cp_commit();
    }

    ull acc[8][5];
    #pragma unroll
    for (int j = 0; j < 8; ++j)
        #pragma unroll
        for (int c = 0; c < 5; ++c) acc[j][c] = 0ull;

    #pragma unroll 1
    for (int ch = 0; ch < 16; ++ch) {
        const int buf = ch & 1;
        cp_wait0();
        __syncthreads();

        const bool st = (ch < 15);
        const u32 ad  = asb + (u32)((buf ^ 1) * 32768) + aswz;
        const float* asrc = A + (row0 + rbase) * 512 + (ch + 1) * 32 + c4 * 4;
        const u32 bd  = bsb + (u32)((buf ^ 1) * 6144 + tid * 16);
        const ull* bsrc = Wp + (size_t)(ch + 1) * 768 + tid * 2;

        const float* as = As + buf * 8192 + lane * 32;
        const ull*   bs = Bs + buf * 768 + w * 6;
        #pragma unroll
        for (int kp2 = 0; kp2 < 8; ++kp2) {
            if (st) {
                cp16(ad + (u32)(kp2 * 4096), asrc + kp2 * 32 * 512);
                if (kp2 == 0) cp16(bd, bsrc);
                if (kp2 == 1 && tid < 128) cp16(bd + 4096, bsrc + 512);
            }
            ull b0[5], b1[5];
            {
                const ull* p0 = bs + (2 * kp2) * 48;
                const ull* p1 = p0 + 48;
                ulonglong2 q;
                q = *(const ulonglong2*)(p0);     b0[0]=q.x; b0[1]=q.y;
                q = *(const ulonglong2*)(p0 + 2); b0[2]=q.x; b0[3]=q.y;
                b0[4] = p0[4];
                q = *(const ulonglong2*)(p1);     b1[0]=q.x; b1[1]=q.y;
                q = *(const ulonglong2*)(p1 + 2); b1[2]=q.x; b1[3]=q.y;
                b1[4] = p1[4];
            }
            const int swoff = (kp2 ^ (lane & 7)) << 2;
            #pragma unroll
            for (int j = 0; j < 8; ++j) {
                ulonglong2 a = *(const ulonglong2*)(as + j * 1024 + swoff);
                #pragma unroll
                for (int c = 0; c < 5; ++c) {
                    ffma2(acc[j][c], a.x, b0[c]);
                    ffma2(acc[j][c], a.y, b1[c]);
                }
            }
        }
        if (st) cp_commit();
    }

    // partials -> smem exchange (overlays As; all A reads done after sync)
    __syncthreads();
    float* so = As;                           // [256][41]
    #pragma unroll
    for (int j = 0; j < 8; ++j)
        #pragma unroll
        for (int c = 0; c < 5; ++c) {
            float lo, hi; upk2(acc[j][c], lo, hi);
            so[(lane + 32 * j) * 41 + w * 5 + c] = lo + hi;
        }
    __syncthreads();

    {   // lane-per-row softmax: warp w handles rows w*32..w*32+31
        const int row = w * 32 + lane;
        float v[40];
        float m = -INFINITY;
        #pragma unroll
        for (int c = 0; c < 40; ++c) { v[c] = so[row * 41 + c]; m = fmaxf(m, v[c]); }
        float s = 0.f;
        #pragma unroll
        for (int c = 0; c < 40; ++c) s += expf(v[c] - m);
        float lse = m + logf(s);
        #pragma unroll
        for (int c = 0; c < 40; ++c) so[row * 41 + c] = v[c] - lse;
    }
    __syncthreads();

    // coalesced copy-out with n-guard
    const int total = (int)min((size_t)256, (size_t)n - row0) * 40;
    for (int e = tid; e < total; e += 256) {
        int r = e / 40, c = e % 40;
        out[row0 * 40 + e] = so[r * 41 + c];
    }
}

// ---------------------------------------------------------------------------
extern "C" void kernel_launch(void* const* d_in, const int* in_sizes, int n_in,
                              void* d_out, int out_size)
{
    const float* x   = (const float*)d_in[0];
    const int*   ptr = (const int*)  d_in[1];
    const int*   idx = (const int*)  d_in[2];
    const int*   rel = (const int*)  d_in[3];
    const float* W1  = (const float*)d_in[4];   // [512][64]
    const float* W2  = (const float*)d_in[5];   // [512][40]
    float* out = (float*)d_out;

    const int n = in_sizes[1] - 1;

    float *agg, *h;
    ull *w1p, *w2p;
    cudaGetSymbolAddress((void**)&agg, g_agg);
    cudaGetSymbolAddress((void**)&h,   g_h);
    cudaGetSymbolAddress((void**)&w1p, g_W1p);
    cudaGetSymbolAddress((void**)&w2p, g_W2p);

    const int agg_grid  = (n + 7) / 8;          // warp per node, 8 warps/block
    const int gemm_grid = (n + 255) / 256;      // 293

    const int s1 = 32768 * 4 + 2 * 2048 * 8;    // 163840
    const int s2 = 16384 * 4 + 2 * 768 * 8;     //  77824
    cudaFuncSetAttribute(gemm1_kernel, cudaFuncAttributeMaxDynamicSharedMemorySize, s1);
    cudaFuncSetAttribute(gemm2_kernel, cudaFuncAttributeMaxDynamicSharedMemorySize, s2);

    prep_kernel<<<104, 256>>>(W1, W2, w1p, w2p);
    agg_kernel<<<agg_grid, 256>>>(x, ptr, idx, rel, agg, n);
    gemm1_kernel<<<gemm_grid, 256, s1>>>(agg, w1p, h, n);
    agg_kernel<<<agg_grid, 256>>>(h, ptr, idx, rel, agg, n);
    gemm2_kernel<<<gemm_grid, 256, s2>>>(agg, w2p, out, n);
}

// round 16
// speedup vs baseline: 1.1933x; 1.1933x over previous
#include <cuda_runtime.h>
#include <math.h>

typedef unsigned long long ull;
typedef unsigned int u32;

#define MAXN_PAD 75008   // 293 blocks * 256 rows

// Global scratch (static __device__ arrays: never allocated at runtime)
__device__ float g_agg[(size_t)MAXN_PAD * 512];   // 153.6 MB
__device__ float g_h  [(size_t)MAXN_PAD * 64];    // 19.2 MB
__device__ ull   g_W1p[256 * 64];                 // W1 k-pair packed [kp][64]
__device__ ull   g_W2p[16 * 16 * 48];             // W2 packed [ch][kp][48] (pad 6/grp)

__device__ __forceinline__ ull pk2(float x, float y) {
    ull r; asm("mov.b64 %0, {%1, %2};" : "=l"(r) : "f"(x), "f"(y)); return r;
}
__device__ __forceinline__ void upk2(ull v, float& x, float& y) {
    asm("mov.b64 {%0, %1}, %2;" : "=f"(x), "=f"(y) : "l"(v));
}
__device__ __forceinline__ void ffma2(ull& d, ull a, ull b) {
    asm("fma.rn.f32x2 %0, %1, %2, %0;" : "+l"(d) : "l"(a), "l"(b));
}
__device__ __forceinline__ void fadd2(ull& d, ull a) {
    asm("add.rn.f32x2 %0, %0, %1;" : "+l"(d) : "l"(a));
}
__device__ __forceinline__ u32 smem_u32(const void* p) {
    u32 a;
    asm("{ .reg .u64 t; cvta.to.shared.u64 t, %1; cvt.u32.u64 %0, t; }" : "=r"(a) : "l"(p));
    return a;
}
__device__ __forceinline__ void cp16(u32 dst, const void* src) {
    asm volatile("cp.async.cg.shared.global [%0], [%1], 16;" :: "r"(dst), "l"(src));
}
__device__ __forceinline__ void cp_commit() { asm volatile("cp.async.commit_group;"); }
__device__ __forceinline__ void cp_wait0()  { asm volatile("cp.async.wait_group 0;"); }

// streaming store: evict-first, don't pollute L2 (zero register cost)
__device__ __forceinline__ void stcs(float* p, ull v) {
    asm volatile("st.global.cs.b64 [%0], %1;" :: "l"(p), "l"(v) : "memory");
}

// ---------------------------------------------------------------------------
// W prep (single launch): k-pair pack both weights into GEMM SMEM layout
// ---------------------------------------------------------------------------
__global__ void prep_kernel(const float* __restrict__ W1, const float* __restrict__ W2,
                            ull* __restrict__ Wp1, ull* __restrict__ Wp2)
{
    int b = blockIdx.x;
    if (b < 64) {
        int i = b * 256 + threadIdx.x;           // 16384
        int kp = i >> 6, c = i & 63;
        Wp1[i] = pk2(W1[(size_t)(2 * kp) * 64 + c], W1[(size_t)(2 * kp + 1) * 64 + c]);
    } else {
        int i = (b - 64) * 256 + threadIdx.x;    // 10240
        if (i < 256 * 40) {
            int kp = i / 40, c = i % 40;
            int ch = kp >> 4, kl = kp & 15;
            Wp2[ch * 768 + kl * 48 + (c / 5) * 6 + (c % 5)] =
                pk2(W2[(size_t)(2 * kp) * 40 + c], W2[(size_t)(2 * kp + 1) * 40 + c]);
        }
    }
}

// ---------------------------------------------------------------------------
// Aggregation: one warp per node (pipelined ballot gather) — R13 structure,
// with .cs (evict-first) output stores as the ONLY change.
// agg[node][r*64+d] = sum_{e: rel_e=r} x[src_e][d]
// ---------------------------------------------------------------------------
__global__ void __launch_bounds__(256)
agg_kernel(const float* __restrict__ xin,
           const int*   __restrict__ ptr,
           const int*   __restrict__ idx,
           const int*   __restrict__ rel,
           float*       __restrict__ agg,
           int n)
{
    const int node = (blockIdx.x * blockDim.x + threadIdx.x) >> 5;
    const int lane = threadIdx.x & 31;
    if (node >= n) return;

    ull acc[8];
    #pragma unroll
    for (int r = 0; r < 8; ++r) acc[r] = 0ull;

    const int e0 = ptr[node], e1 = ptr[node + 1];
    for (int eb = e0; eb < e1; eb += 32) {
        const int cnt = min(32, e1 - eb);
        int mi = 0, mr = -1;
        if (lane < cnt) { mi = idx[eb + lane]; mr = rel[eb + lane]; }
        #pragma unroll
        for (int r = 0; r < 8; ++r) {
            unsigned m = __ballot_sync(0xffffffffu, mr == r);
            if (!m) continue;
            int t = __ffs(m) - 1; m &= m - 1;
            int s = __shfl_sync(0xffffffffu, mi, t);
            ull v = *(const ull*)(xin + (size_t)s * 64 + 2 * lane);
            while (m) {
                int t2 = __ffs(m) - 1; m &= m - 1;
                int s2 = __shfl_sync(0xffffffffu, mi, t2);
                ull v2 = *(const ull*)(xin + (size_t)s2 * 64 + 2 * lane);
                fadd2(acc[r], v);          // v in flight while v2 loads
                v = v2;
            }
            fadd2(acc[r], v);
        }
    }

    float* arow = agg + (size_t)node * 512;
    #pragma unroll
    for (int r = 0; r < 8; ++r)
        stcs(arow + r * 64 + 2 * lane, acc[r]);
}

// ---------------------------------------------------------------------------
// GEMM layer 1: H[256 x 64]/block = relu(A[256 x 512] @ W1), 8 chunks of K=64.
// 256 thr, 8 warps, tile 8x8. cp.async issue interleaved into the kp2 loop.
// ---------------------------------------------------------------------------
__global__ void __launch_bounds__(256, 1)
gemm1_kernel(const float* __restrict__ A,
             const ull*   __restrict__ Wp,   // [256 kp][64] packed
             float*       __restrict__ out,  // g_h
             int n)
{
    extern __shared__ float sm[];
    float* As = sm;                          // [2][16384] floats
    ull*   Bs = (ull*)(sm + 32768);          // [2][2048] ull
    const u32 asb = smem_u32(As);
    const u32 bsb = smem_u32(Bs);

    const int tid  = threadIdx.x;
    const int lane = tid & 31;
    const int w    = tid >> 5;
    const size_t row0 = (size_t)blockIdx.x * 256;

    const int rbase = tid >> 4;              // 0..15 (A stage row base)
    const int c4    = tid & 15;
    const u32 aswz  = (u32)((rbase * 64 + ((c4 ^ (rbase & 7)) << 2)) * 4);

    // bunched prologue stage of chunk 0
    {
        #pragma unroll
        for (int i = 0; i < 16; ++i)
            cp16(asb + aswz + (u32)(i * 4096),
                 A + (row0 + rbase + i * 16) * 512 + c4 * 4);
        #pragma unroll
        for (int i = 0; i < 4; ++i)
            cp16(bsb + (u32)((tid + i * 256) * 16), Wp + (tid + i * 256) * 2);
        cp_commit();
    }

    ull acc[8][8];
    #pragma unroll
    for (int j = 0; j < 8; ++j)
        #pragma unroll
        for (int c = 0; c < 8; ++c) acc[j][c] = 0ull;

    #pragma unroll 1
    for (int ch = 0; ch < 8; ++ch) {
        const int buf = ch & 1;
        cp_wait0();
        __syncthreads();

        const bool st = (ch < 7);
        const u32 ad  = asb + (u32)((buf ^ 1) * 65536) + aswz;
        const float* asrc = A + (row0 + rbase) * 512 + (ch + 1) * 64 + c4 * 4;
        const u32 bd  = bsb + (u32)((buf ^ 1) * 16384 + tid * 16);
        const ull* bsrc = Wp + (size_t)(ch + 1) * 2048 + tid * 2;

        const float* as = As + buf * 16384 + lane * 64;
        const ull*   bs = Bs + buf * 2048 + w * 8;
        #pragma unroll
        for (int kp2 = 0; kp2 < 16; ++kp2) {
            if (st) {
                cp16(ad + (u32)(kp2 * 4096), asrc + kp2 * 16 * 512);
                if (kp2 < 4)
                    cp16(bd + (u32)(kp2 * 4096), bsrc + kp2 * 512);
            }
            ulonglong2 q;
            ull b0[8], b1[8];
            q = *(const ulonglong2*)(bs + (2 * kp2) * 64 + 0); b0[0]=q.x; b0[1]=q.y;
            q = *(const ulonglong2*)(bs + (2 * kp2) * 64 + 2); b0[2]=q.x; b0[3]=q.y;
            q = *(const ulonglong2*)(bs + (2 * kp2) * 64 + 4); b0[4]=q.x; b0[5]=q.y;
            q = *(const ulonglong2*)(bs + (2 * kp2) * 64 + 6); b0[6]=q.x; b0[7]=q.y;
            q = *(const ulonglong2*)(bs + (2 * kp2 + 1) * 64 + 0); b1[0]=q.x; b1[1]=q.y;
            q = *(const ulonglong2*)(bs + (2 * kp2 + 1) * 64 + 2); b1[2]=q.x; b1[3]=q.y;
            q = *(const ulonglong2*)(bs + (2 * kp2 + 1) * 64 + 4); b1[4]=q.x; b1[5]=q.y;
            q = *(const ulonglong2*)(bs + (2 * kp2 + 1) * 64 + 6); b1[6]=q.x; b1[7]=q.y;
            const int swoff = (kp2 ^ (lane & 7)) << 2;
            #pragma unroll
            for (int j = 0; j < 8; ++j) {
                ulonglong2 a = *(const ulonglong2*)(as + j * 2048 + swoff);
                #pragma unroll
                for (int c = 0; c < 8; ++c) {
                    ffma2(acc[j][c], a.x, b0[c]);
                    ffma2(acc[j][c], a.y, b1[c]);
                }
            }
        }
        if (st) cp_commit();
    }

    #pragma unroll
    for (int j = 0; j < 8; ++j) {
        size_t g = row0 + lane + 32 * j;
        float lo, hi; float4 o;
        upk2(acc[j][0], lo, hi); o.x = fmaxf(lo + hi, 0.f);
        upk2(acc[j][1], lo, hi); o.y = fmaxf(lo + hi, 0.f);
        upk2(acc[j][2], lo, hi); o.z = fmaxf(lo + hi, 0.f);
        upk2(acc[j][3], lo, hi); o.w = fmaxf(lo + hi, 0.f);
        *(float4*)(out + g * 64 + w * 8) = o;
        upk2(acc[j][4], lo, hi); o.x = fmaxf(lo + hi, 0.f);
        upk2(acc[j][5], lo, hi); o.y = fmaxf(lo + hi, 0.f);
        upk2(acc[j][6], lo, hi); o.z = fmaxf(lo + hi, 0.f);
        upk2(acc[j][7], lo, hi); o.w = fmaxf(lo + hi, 0.f);
        *(float4*)(out + g * 64 + w * 8 + 4) = o;
    }
}

// ---------------------------------------------------------------------------
// GEMM layer 2 + log_softmax: out[256 x 40]/block, 16 chunks of K=32.
// 256 thr, tile 8x5, 2 CTAs/SM. cp.async issue interleaved into kp2 loop.
// ---------------------------------------------------------------------------
__global__ void __launch_bounds__(256, 2)
gemm2_kernel(const float* __restrict__ A,
             const ull*   __restrict__ Wp,   // [16 ch][16 kp][48] packed
             float*       __restrict__ out,  // [n][40]
             int n)
{
    extern __shared__ float sm[];
    float* As = sm;                          // [2][8192] floats (K=32 chunks)
    ull*   Bs = (ull*)(sm + 16384);          // [2][768] ull
    const u32 asb = smem_u32(As);
    const u32 bsb = smem_u32(Bs);

    const int tid  = threadIdx.x;
    const int lane = tid & 31;
    const int w    = tid >> 5;
    const size_t row0 = (size_t)blockIdx.x * 256;

    const int rbase = tid >> 3;              // 0..31
    const int c4    = tid & 7;
    const u32 aswz  = (u32)((rbase * 32 + ((c4 ^ (rbase & 7)) << 2)) * 4);

    {   // prologue stage chunk 0
        #pragma unroll
        for (int i = 0; i < 8; ++i)
            cp16(asb + aswz + (u32)(i * 4096),
                 A + (row0 + rbase + i * 32) * 512 + c4 * 4);
        #pragma unroll
        for (int i = 0; i < 2; ++i) {
            int v = tid + i * 256;
            if (v < 384) cp16(bsb + (u32)(v * 16), Wp + v * 2);
        }
        cp_commit();
    }

    ull acc[8][5];
    #pragma unroll
    for (int j = 0; j < 8; ++j)
        #pragma unroll
        for (int c = 0; c < 5; ++c) acc[j][c] = 0ull;

    #pragma unroll 1
    for (int ch = 0; ch < 16; ++ch) {
        const int buf = ch & 1;
        cp_wait0();
        __syncthreads();

        const bool st = (ch < 15);
        const u32 ad  = asb + (u32)((buf ^ 1) * 32768) + aswz;
        const float* asrc = A + (row0 + rbase) * 512 + (ch + 1) * 32 + c4 * 4;
        const u32 bd  = bsb + (u32)((buf ^ 1) * 6144 + tid * 16);
        const ull* bsrc = Wp + (size_t)(ch + 1) * 768 + tid * 2;

        const float* as = As + buf * 8192 + lane * 32;
        const ull*   bs = Bs + buf * 768 + w * 6;
        #pragma unroll
        for (int kp2 = 0; kp2 < 8; ++kp2) {
            if (st) {
                cp16(ad + (u32)(kp2 * 4096), asrc + kp2 * 32 * 512);
                if (kp2 == 0) cp16(bd, bsrc);
                if (kp2 == 1 && tid < 128) cp16(bd + 4096, bsrc + 512);
            }
            ull b0[5], b1[5];
            {
                const ull* p0 = bs + (2 * kp2) * 48;
                const ull* p1 = p0 + 48;
                ulonglong2 q;
                q = *(const ulonglong2*)(p0);     b0[0]=q.x; b0[1]=q.y;
                q = *(const ulonglong2*)(p0 + 2); b0[2]=q.x; b0[3]=q.y;
                b0[4] = p0[4];
                q = *(const ulonglong2*)(p1);     b1[0]=q.x; b1[1]=q.y;
                q = *(const ulonglong2*)(p1 + 2); b1[2]=q.x; b1[3]=q.y;
                b1[4] = p1[4];
            }
            const int swoff = (kp2 ^ (lane & 7)) << 2;
            #pragma unroll
            for (int j = 0; j < 8; ++j) {
                ulonglong2 a = *(const ulonglong2*)(as + j * 1024 + swoff);
                #pragma unroll
                for (int c = 0; c < 5; ++c) {
                    ffma2(acc[j][c], a.x, b0[c]);
                    ffma2(acc[j][c], a.y, b1[c]);
                }
            }
        }
        if (st) cp_commit();
    }

    // partials -> smem exchange (overlays As; all A reads done after sync)
    __syncthreads();
    float* so = As;                           // [256][41]
    #pragma unroll
    for (int j = 0; j < 8; ++j)
        #pragma unroll
        for (int c = 0; c < 5; ++c) {
            float lo, hi; upk2(acc[j][c], lo, hi);
            so[(lane + 32 * j) * 41 + w * 5 + c] = lo + hi;
        }
    __syncthreads();

    {   // lane-per-row softmax: warp w handles rows w*32..w*32+31
        const int row = w * 32 + lane;
        float v[40];
        float m = -INFINITY;
        #pragma unroll
        for (int c = 0; c < 40; ++c) { v[c] = so[row * 41 + c]; m = fmaxf(m, v[c]); }
        float s = 0.f;
        #pragma unroll
        for (int c = 0; c < 40; ++c) s += expf(v[c] - m);
        float lse = m + logf(s);
        #pragma unroll
        for (int c = 0; c < 40; ++c) so[row * 41 + c] = v[c] - lse;
    }
    __syncthreads();

    // coalesced copy-out with n-guard
    const int total = (int)min((size_t)256, (size_t)n - row0) * 40;
    for (int e = tid; e < total; e += 256) {
        int r = e / 40, c = e % 40;
        out[row0 * 40 + e] = so[r * 41 + c];
    }
}

// ---------------------------------------------------------------------------
extern "C" void kernel_launch(void* const* d_in, const int* in_sizes, int n_in,
                              void* d_out, int out_size)
{
    const float* x   = (const float*)d_in[0];
    const int*   ptr = (const int*)  d_in[1];
    const int*   idx = (const int*)  d_in[2];
    const int*   rel = (const int*)  d_in[3];
    const float* W1  = (const float*)d_in[4];   // [512][64]
    const float* W2  = (const float*)d_in[5];   // [512][40]
    float* out = (float*)d_out;

    const int n = in_sizes[1] - 1;

    float *agg, *h;
    ull *w1p, *w2p;
    cudaGetSymbolAddress((void**)&agg, g_agg);
    cudaGetSymbolAddress((void**)&h,   g_h);
    cudaGetSymbolAddress((void**)&w1p, g_W1p);
    cudaGetSymbolAddress((void**)&w2p, g_W2p);

    const int agg_grid  = (n + 7) / 8;          // warp per node, 8 warps/block
    const int gemm_grid = (n + 255) / 256;      // 293

    const int s1 = 32768 * 4 + 2 * 2048 * 8;    // 163840
    const int s2 = 16384 * 4 + 2 * 768 * 8;     //  77824
    cudaFuncSetAttribute(gemm1_kernel, cudaFuncAttributeMaxDynamicSharedMemorySize, s1);
    cudaFuncSetAttribute(gemm2_kernel, cudaFuncAttributeMaxDynamicSharedMemorySize, s2);

    prep_kernel<<<104, 256>>>(W1, W2, w1p, w2p);
    agg_kernel<<<agg_grid, 256>>>(x, ptr, idx, rel, agg, n);
    gemm1_kernel<<<gemm_grid, 256, s1>>>(agg, w1p, h, n);
    agg_kernel<<<agg_grid, 256>>>(h, ptr, idx, rel, agg, n);
    gemm2_kernel<<<gemm_grid, 256, s2>>>(agg, w2p, out, n);
}